// round 6
// baseline (speedup 1.0000x reference)
#include <cuda_runtime.h>
#include <math.h>

#define BB 32
#define LL 196
#define DD 512
#define HH 512
#define EE 256
#define TT 128
#define VV 512
#define A1 256
#define A2 128
#define GG 2048            // 4*H
#define NH 358
#define HZE (HH + DD + EE) // 1280
#define NPG (A1 + GG)      // 2304
#define PADTOK 0

// ---------------- scratch (no allocation allowed) ----------------
__device__ float g_eseq[BB * TT * EE];
__device__ float g_prea[BB * LL * A1];
__device__ float g_egate[BB * TT * GG];
__device__ float g_h[BB * HH];
__device__ float g_c[BB * HH];
__device__ float g_hpg[BB * NPG];
__device__ float g_scores[BB * LL];
__device__ float g_z[BB * DD];
__device__ float g_hze[BB * TT * HZE];
__device__ float g_x1[BB * TT * NH];
__device__ float g_x2[BB * TT * NH];

// ---------------- init h,c ----------------
__global__ void k_init_hc(const float* __restrict__ h0, const float* __restrict__ c0) {
    int i = blockIdx.x * 256 + threadIdx.x;
    if (i < BB * HH) { g_h[i] = h0[i]; g_c[i] = c0[i]; }
}

// ---------------- embedding gather (shift-right w/ pad) ----------------
__global__ void k_embed(const int* __restrict__ y, const float* __restrict__ embed) {
    int bt = blockIdx.x;                 // b*T + t
    int b = bt / TT, t = bt % TT;
    int tok = (t == 0) ? PADTOK : y[b * TT + (t - 1)];
    float v = embed[tok * EE + threadIdx.x];
    g_eseq[bt * EE + threadIdx.x] = v;
    g_hze[bt * HZE + HH + DD + threadIdx.x] = v;   // e part of hze
}

// ---------------- generic tiled SGEMM: C = act(A*W + bias) ----------------
template <int ACT>
__global__ void k_sgemm(const float* __restrict__ A, int lda,
                        const float* __restrict__ W, int ldw,
                        const float* __restrict__ bias,
                        float* __restrict__ C, int ldc,
                        int M, int N, int K) {
    __shared__ float As[16][65];
    __shared__ float Ws[16][65];
    int tx = threadIdx.x % 16, ty = threadIdx.x / 16;
    int row0 = blockIdx.y * 64;
    int col0 = blockIdx.x * 64;
    float acc[4][4] = {};
    for (int k0 = 0; k0 < K; k0 += 16) {
        for (int i = threadIdx.x; i < 64 * 16; i += 256) {
            int r = i >> 4, kk = i & 15;
            int gr = row0 + r, gk = k0 + kk;
            As[kk][r] = (gr < M && gk < K) ? A[gr * lda + gk] : 0.f;
        }
        for (int i = threadIdx.x; i < 16 * 64; i += 256) {
            int kk = i >> 6, c = i & 63;
            int gk = k0 + kk, gc = col0 + c;
            Ws[kk][c] = (gk < K && gc < N) ? W[gk * ldw + gc] : 0.f;
        }
        __syncthreads();
#pragma unroll
        for (int kk = 0; kk < 16; kk++) {
            float a_[4], w_[4];
#pragma unroll
            for (int i = 0; i < 4; i++) a_[i] = As[kk][ty * 4 + i];
#pragma unroll
            for (int j = 0; j < 4; j++) w_[j] = Ws[kk][tx * 4 + j];
#pragma unroll
            for (int i = 0; i < 4; i++)
#pragma unroll
                for (int j = 0; j < 4; j++) acc[i][j] += a_[i] * w_[j];
        }
        __syncthreads();
    }
#pragma unroll
    for (int i = 0; i < 4; i++) {
        int r = row0 + ty * 4 + i;
        if (r >= M) continue;
#pragma unroll
        for (int j = 0; j < 4; j++) {
            int c = col0 + tx * 4 + j;
            if (c >= N) continue;
            float v = acc[i][j] + (bias ? bias[c] : 0.f);
            if (ACT == 1) v = tanhf(v);
            C[r * ldc + c] = v;
        }
    }
}

// ---------------- per-step K1: h projections (EXACT passing version) ----------------
__global__ void k_proj(const float* __restrict__ w1h,   // att_w1 + D*A1 (ld A1)
                       const float* __restrict__ whh,   // ld GG
                       const float* __restrict__ bhh) {
    int n = blockIdx.x * 128 + threadIdx.x;  // 0..2303
    int m0 = blockIdx.y * 4;                 // 4 batch rows per block
    __shared__ float hs[4][HH];
    for (int i = threadIdx.x; i < 4 * HH; i += 128)
        hs[i / HH][i % HH] = g_h[(m0 + i / HH) * HH + (i % HH)];
    __syncthreads();
    if (n >= NPG) return;
    const float* W; int ld, col; float bias;
    if (n < A1) { W = w1h; ld = A1; col = n; bias = 0.f; }
    else        { W = whh; ld = GG; col = n - A1; bias = bhh[n - A1]; }
    float a0 = bias, a1 = bias, a2 = bias, a3 = bias;
#pragma unroll 4
    for (int k = 0; k < HH; k++) {
        float w = W[k * ld + col];
        a0 += hs[0][k] * w; a1 += hs[1][k] * w;
        a2 += hs[2][k] * w; a3 += hs[3][k] * w;
    }
    g_hpg[(m0 + 0) * NPG + n] = a0;
    g_hpg[(m0 + 1) * NPG + n] = a1;
    g_hpg[(m0 + 2) * NPG + n] = a2;
    g_hpg[(m0 + 3) * NPG + n] = a3;
}

// ---------------- per-step K2: attention scores (16-row tiles) ----------------
// block = (l-tile of 16, b), 128 threads; thread tid = output column n (A2=128).
// x1 tile (16 x 256) staged in smem with tanh; inner loop: w2 scalar load (L1),
// x1s read as float4 from SHARED memory only (alignment guaranteed).
__global__ void k_att(const float* __restrict__ w2, const float* __restrict__ b2,
                      const float* __restrict__ w3, const float* __restrict__ b3) {
    __shared__ float x1s[16][A1];   // 16 KB
    __shared__ float hps[A1];       // 1 KB
    __shared__ float red[16][4];
    int b = blockIdx.y;
    int l0 = blockIdx.x * 16;
    int tid = threadIdx.x;          // 0..127
    int lane = tid & 31, warp = tid >> 5;

    for (int i = tid; i < A1; i += 128) hps[i] = g_hpg[b * NPG + i];
    __syncthreads();
    for (int idx = tid; idx < 16 * A1; idx += 128) {
        int r = idx >> 8, k = idx & 255;
        int l = l0 + r;
        float v = 0.f;
        if (l < LL) v = tanhf(g_prea[(b * LL + l) * A1 + k] + hps[k]);
        x1s[r][k] = v;
    }
    __syncthreads();

    float acc[16];
    float bias2 = b2[tid];
#pragma unroll
    for (int r = 0; r < 16; r++) acc[r] = bias2;

    for (int k4 = 0; k4 < A1 / 4; k4++) {
        int k = k4 * 4;
        float w0 = w2[(k + 0) * A2 + tid];
        float w1 = w2[(k + 1) * A2 + tid];
        float wv2 = w2[(k + 2) * A2 + tid];
        float wv3 = w2[(k + 3) * A2 + tid];
#pragma unroll
        for (int r = 0; r < 16; r++) {
            float4 xv = *reinterpret_cast<const float4*>(&x1s[r][k]);
            acc[r] += xv.x * w0 + xv.y * w1 + xv.z * wv2 + xv.w * wv3;
        }
    }

    // x2 = tanh(acc); partial score = x2 * w3[col]; reduce over 128 cols
    float w3v = w3[tid];
#pragma unroll
    for (int r = 0; r < 16; r++) {
        float p = tanhf(acc[r]) * w3v;
#pragma unroll
        for (int off = 16; off; off >>= 1)
            p += __shfl_down_sync(0xffffffffu, p, off);
        if (lane == 0) red[r][warp] = p;
    }
    __syncthreads();
    if (tid < 16) {
        int l = l0 + tid;
        if (l < LL) {
            float s = red[tid][0] + red[tid][1] + red[tid][2] + red[tid][3] + b3[0];
            g_scores[b * LL + l] = s;
        }
    }
}

// ---------------- per-step K3: softmax + context z (grid (2,B), 256 thr) ----------------
__global__ void k_soft_z(const float* __restrict__ a, int t) {
    int s = blockIdx.x;          // d-chunk: 0 or 1
    int b = blockIdx.y;
    __shared__ float al[LL];
    __shared__ float rbuf[8];
    int tid = threadIdx.x, lane = tid & 31, warp = tid >> 5;
    float v = (tid < LL) ? g_scores[b * LL + tid] : -1e30f;
    float m = v;
#pragma unroll
    for (int off = 16; off; off >>= 1) m = fmaxf(m, __shfl_xor_sync(0xffffffffu, m, off));
    if (lane == 0) rbuf[warp] = m;
    __syncthreads();
    m = rbuf[0];
#pragma unroll
    for (int i = 1; i < 8; i++) m = fmaxf(m, rbuf[i]);
    float e = (tid < LL) ? expf(v - m) : 0.f;
    __syncthreads();
    float sum = e;
#pragma unroll
    for (int off = 16; off; off >>= 1) sum += __shfl_xor_sync(0xffffffffu, sum, off);
    if (lane == 0) rbuf[warp] = sum;
    __syncthreads();
    sum = rbuf[0] + rbuf[1] + rbuf[2] + rbuf[3] + rbuf[4] + rbuf[5] + rbuf[6] + rbuf[7];
    float inv = 1.f / sum;
    if (tid < LL) al[tid] = e * inv;
    __syncthreads();
    int d = s * 256 + tid;       // 0..511
    float acc = 0.f;
    const float* ab = a + (size_t)(b * LL) * DD + d;
#pragma unroll 4
    for (int l = 0; l < LL; l++) acc += al[l] * ab[l * DD];
    g_z[b * DD + d] = acc;
    g_hze[(size_t)(b * TT + t) * HZE + HH + d] = acc;
}

// ---------------- per-step K4: LSTM gates from z + update (4-batch blocked) ----------------
__global__ void k_lstm(const float* __restrict__ wih, int t) {
    int jp = blockIdx.x * 128 + threadIdx.x;     // hidden index 0..511
    int m0 = blockIdx.y * 4;                     // 4 batches per block
    __shared__ float zs[4][DD];
    for (int i = threadIdx.x; i < 4 * DD; i += 128) {
        int bi = i >> 9, kk = i & 511;
        zs[bi][kk] = g_z[(m0 + bi) * DD + kk];
    }
    __syncthreads();
    if (jp >= HH) return;
    float acc[4][4] = {};
#pragma unroll 4
    for (int d = 0; d < DD; d++) {
        const float* wr = wih + (size_t)d * GG + jp;
        float wi = wr[0], wf = wr[512], wg = wr[1024], wo = wr[1536];
#pragma unroll
        for (int bi = 0; bi < 4; bi++) {
            float zv = zs[bi][d];
            acc[bi][0] += zv * wi;
            acc[bi][1] += zv * wf;
            acc[bi][2] += zv * wg;
            acc[bi][3] += zv * wo;
        }
    }
#pragma unroll
    for (int bi = 0; bi < 4; bi++) {
        int b = m0 + bi;
        const float* eg = g_egate + (size_t)(b * TT + t) * GG;
        const float* hg = g_hpg + b * NPG + A1;
        float ai = acc[bi][0] + eg[jp]        + hg[jp];
        float af = acc[bi][1] + eg[jp + 512]  + hg[jp + 512];
        float ag = acc[bi][2] + eg[jp + 1024] + hg[jp + 1024];
        float ao = acc[bi][3] + eg[jp + 1536] + hg[jp + 1536];
        float i_ = 1.f / (1.f + expf(-ai));
        float f_ = 1.f / (1.f + expf(-af));
        float o_ = 1.f / (1.f + expf(-ao));
        float gv = tanhf(ag);
        float c = f_ * g_c[b * HH + jp] + i_ * gv;
        float h = o_ * tanhf(c);
        g_c[b * HH + jp] = c;
        g_h[b * HH + jp] = h;
        g_hze[(size_t)(b * TT + t) * HZE + jp] = h;
    }
}

// ---------------- launch ----------------
extern "C" void kernel_launch(void* const* d_in, const int* in_sizes, int n_in,
                              void* d_out, int out_size) {
    const float* a      = (const float*)d_in[0];
    const float* h0     = (const float*)d_in[1];
    const float* c0     = (const float*)d_in[2];
    const int*   y      = (const int*)d_in[3];
    const float* att_w1 = (const float*)d_in[4];
    const float* att_b1 = (const float*)d_in[5];
    const float* att_w2 = (const float*)d_in[6];
    const float* att_b2 = (const float*)d_in[7];
    const float* att_w3 = (const float*)d_in[8];
    const float* att_b3 = (const float*)d_in[9];
    const float* w_ih   = (const float*)d_in[10];
    const float* w_hh   = (const float*)d_in[11];
    const float* b_ih   = (const float*)d_in[12];
    const float* b_hh   = (const float*)d_in[13];
    const float* embed  = (const float*)d_in[14];
    const float* out_w1 = (const float*)d_in[15];
    const float* out_b1 = (const float*)d_in[16];
    const float* out_w2 = (const float*)d_in[17];
    const float* out_b2 = (const float*)d_in[18];
    const float* out_w3 = (const float*)d_in[19];
    const float* out_b3 = (const float*)d_in[20];
    float* out = (float*)d_out;

    float *prea, *eseq, *egate, *hze, *x1, *x2;
    cudaGetSymbolAddress((void**)&prea,  g_prea);
    cudaGetSymbolAddress((void**)&eseq,  g_eseq);
    cudaGetSymbolAddress((void**)&egate, g_egate);
    cudaGetSymbolAddress((void**)&hze,   g_hze);
    cudaGetSymbolAddress((void**)&x1,    g_x1);
    cudaGetSymbolAddress((void**)&x2,    g_x2);

    k_init_hc<<<(BB * HH + 255) / 256, 256>>>(h0, c0);
    k_embed<<<BB * TT, EE>>>(y, embed);

    // pre_a[B*L,256] = a @ att_w1[:D] + b1
    k_sgemm<0><<<dim3((A1 + 63) / 64, (BB * LL + 63) / 64), 256>>>(
        a, DD, att_w1, A1, att_b1, prea, A1, BB * LL, A1, DD);
    // e_gates[B*T,2048] = e_seq @ w_ih[D:] + b_ih
    k_sgemm<0><<<dim3((GG + 63) / 64, (BB * TT + 63) / 64), 256>>>(
        eseq, EE, w_ih + (size_t)DD * GG, GG, b_ih, egate, GG, BB * TT, GG, EE);

    for (int t = 0; t < TT; t++) {
        k_proj<<<dim3(NPG / 128, BB / 4), 128>>>(att_w1 + (size_t)DD * A1, w_hh, b_hh);
        k_att<<<dim3((LL + 15) / 16, BB), 128>>>(att_w2, att_b2, att_w3, att_b3);
        k_soft_z<<<dim3(2, BB), 256>>>(a, t);
        k_lstm<<<dim3(HH / 128, BB / 4), 128>>>(w_ih, t);
    }

    // output MLP: (B*T,1280) -> 358 tanh -> 358 tanh -> V
    k_sgemm<1><<<dim3((NH + 63) / 64, (BB * TT + 63) / 64), 256>>>(
        hze, HZE, out_w1, NH, out_b1, x1, NH, BB * TT, NH, HZE);
    k_sgemm<1><<<dim3((NH + 63) / 64, (BB * TT + 63) / 64), 256>>>(
        x1, NH, out_w2, NH, out_b2, x2, NH, BB * TT, NH, NH);
    k_sgemm<0><<<dim3((VV + 63) / 64, (BB * TT + 63) / 64), 256>>>(
        x2, NH, out_w3, VV, out_b3, out, VV, BB * TT, VV, NH);
}

// round 7
// speedup vs baseline: 1.3419x; 1.3419x over previous
#include <cuda_runtime.h>
#include <math.h>

#define BB 32
#define LL 196
#define DD 512
#define HH 512
#define EE 256
#define TT 128
#define VV 512
#define A1 256
#define A2 128
#define GG 2048            // 4*H
#define NH 358
#define HZE (HH + DD + EE) // 1280
#define NPG (A1 + GG)      // 2304
#define PADTOK 0
#define NBLK 148
#define NTHR 256

// ---------------- scratch (no allocation allowed) ----------------
__device__ float g_eseq[BB * TT * EE];
__device__ float g_prea[BB * LL * A1];
__device__ float g_egate[BB * TT * GG];
__device__ float g_h[BB * HH];
__device__ float g_c[BB * HH];
__device__ float g_hpg[BB * NPG];
__device__ float g_scores[BB * LL];
__device__ float g_z[BB * DD];
__device__ float g_hze[BB * TT * HZE];
__device__ float g_x1[BB * TT * NH];
__device__ float g_x2[BB * TT * NH];

// ---------------- software grid barrier (sense via generation counter) ----
// Self-consistent across graph replays: count always returns to 0 at the end
// of each barrier; gen monotonically increases (wraparound harmless).
__device__ unsigned g_bar_count;
__device__ volatile unsigned g_bar_gen;

__device__ __forceinline__ void grid_sync() {
    __syncthreads();
    if (threadIdx.x == 0) {
        unsigned gen = g_bar_gen;
        __threadfence();
        if (atomicAdd(&g_bar_count, 1u) == NBLK - 1) {
            g_bar_count = 0;
            __threadfence();
            g_bar_gen = gen + 1;
        } else {
            while (g_bar_gen == gen) {}
        }
        __threadfence();
    }
    __syncthreads();
}

// ---------------- embedding gather (shift-right w/ pad) ----------------
__global__ void k_embed(const int* __restrict__ y, const float* __restrict__ embed) {
    int bt = blockIdx.x;                 // b*T + t
    int b = bt / TT, t = bt % TT;
    int tok = (t == 0) ? PADTOK : y[b * TT + (t - 1)];
    float v = embed[tok * EE + threadIdx.x];
    g_eseq[bt * EE + threadIdx.x] = v;
    g_hze[bt * HZE + HH + DD + threadIdx.x] = v;   // e part of hze
}

// ---------------- generic tiled SGEMM: C = act(A*W + bias) ----------------
template <int ACT>
__global__ void k_sgemm(const float* __restrict__ A, int lda,
                        const float* __restrict__ W, int ldw,
                        const float* __restrict__ bias,
                        float* __restrict__ C, int ldc,
                        int M, int N, int K) {
    __shared__ float As[16][65];
    __shared__ float Ws[16][65];
    int tx = threadIdx.x % 16, ty = threadIdx.x / 16;
    int row0 = blockIdx.y * 64;
    int col0 = blockIdx.x * 64;
    float acc[4][4] = {};
    for (int k0 = 0; k0 < K; k0 += 16) {
        for (int i = threadIdx.x; i < 64 * 16; i += 256) {
            int r = i >> 4, kk = i & 15;
            int gr = row0 + r, gk = k0 + kk;
            As[kk][r] = (gr < M && gk < K) ? A[gr * lda + gk] : 0.f;
        }
        for (int i = threadIdx.x; i < 16 * 64; i += 256) {
            int kk = i >> 6, c = i & 63;
            int gk = k0 + kk, gc = col0 + c;
            Ws[kk][c] = (gk < K && gc < N) ? W[gk * ldw + gc] : 0.f;
        }
        __syncthreads();
#pragma unroll
        for (int kk = 0; kk < 16; kk++) {
            float a_[4], w_[4];
#pragma unroll
            for (int i = 0; i < 4; i++) a_[i] = As[kk][ty * 4 + i];
#pragma unroll
            for (int j = 0; j < 4; j++) w_[j] = Ws[kk][tx * 4 + j];
#pragma unroll
            for (int i = 0; i < 4; i++)
#pragma unroll
                for (int j = 0; j < 4; j++) acc[i][j] += a_[i] * w_[j];
        }
        __syncthreads();
    }
#pragma unroll
    for (int i = 0; i < 4; i++) {
        int r = row0 + ty * 4 + i;
        if (r >= M) continue;
#pragma unroll
        for (int j = 0; j < 4; j++) {
            int c = col0 + tx * 4 + j;
            if (c >= N) continue;
            float v = acc[i][j] + (bias ? bias[c] : 0.f);
            if (ACT == 1) v = tanhf(v);
            C[r * ldc + c] = v;
        }
    }
}

// ---------------- persistent step-loop kernel ----------------
struct SmemA { float h4[4][HH]; };                                 // 8 KB
struct SmemB { float x1[32][A1]; float w2t[16][A2]; float hp[A1]; }; // 41 KB
struct SmemC { float al[LL]; float red[8]; };                      // ~0.8 KB
struct SmemD { float z4[4][DD]; float gacc[4][64][4]; };           // 12 KB
union StepSmem { SmemA a; SmemB b; SmemC c; SmemD d; };

__global__ __launch_bounds__(NTHR, 1)
void k_steps(const float* __restrict__ a_feat,
             const float* __restrict__ h0, const float* __restrict__ c0,
             const float* __restrict__ w1h,   // att_w1 + D*A1 (ld A1)
             const float* __restrict__ whh,   // ld GG
             const float* __restrict__ bhh,
             const float* __restrict__ w2, const float* __restrict__ b2,
             const float* __restrict__ w3, const float* __restrict__ b3,
             const float* __restrict__ wih) {
    __shared__ StepSmem sm;
    int bid = blockIdx.x;
    int tid = threadIdx.x;

    // init h, c
    for (int i = bid * NTHR + tid; i < BB * HH; i += NBLK * NTHR) {
        g_h[i] = h0[i];
        g_c[i] = c0[i];
    }
    grid_sync();

    for (int t = 0; t < TT; t++) {
        // ---- Phase A: hpg[b, 0:256] = h@w1h ; hpg[b, 256:2304] = h@whh + bhh
        // 144 units = 18 col-chunks(128) x 8 batch-groups(4)
        if (bid < 144) {
            int nch = bid / 8;          // 0..17
            int bg = bid % 8;           // 0..7 -> batches bg*4..bg*4+3
            for (int i = tid; i < 4 * HH; i += NTHR) {
                int bi = i >> 9, kk = i & 511;
                sm.a.h4[bi][kk] = g_h[(bg * 4 + bi) * HH + kk];
            }
            __syncthreads();
            int c = tid & 127;
            int half = tid >> 7;        // 0/1 -> batches half*2, half*2+1
            int n = nch * 128 + c;      // 0..2303
            const float* W; int ld, col; float bias;
            if (n < A1) { W = w1h; ld = A1; col = n; bias = 0.f; }
            else        { W = whh; ld = GG; col = n - A1; bias = bhh[n - A1]; }
            int b0 = half * 2;
            float a0 = bias, a1 = bias;
#pragma unroll 4
            for (int k = 0; k < HH; k++) {
                float w = W[k * ld + col];
                a0 += sm.a.h4[b0][k] * w;
                a1 += sm.a.h4[b0 + 1][k] * w;
            }
            g_hpg[(bg * 4 + b0) * NPG + n] = a0;
            g_hpg[(bg * 4 + b0 + 1) * NPG + n] = a1;
        }
        grid_sync();

        // ---- Phase B: attention scores. 224 units = 32 b x 7 l-tiles(32)
        for (int u = bid; u < 224; u += NBLK) {
            int b = u / 7;
            int l0 = (u % 7) * 32;
            sm.b.hp[tid] = g_hpg[b * NPG + tid];   // tid < 256 == A1
            __syncthreads();
            for (int idx = tid; idx < 32 * A1; idx += NTHR) {
                int r = idx >> 8, k = idx & 255;
                int l = l0 + r;
                float v = 0.f;
                if (l < LL) v = tanhf(g_prea[(b * LL + l) * A1 + k] + sm.b.hp[k]);
                sm.b.x1[r][k] = v;
            }
            __syncthreads();
            int tx = tid & 31, ty = tid >> 5;       // warp ty handles rows ty*4..+3
            float acc[4][4] = {};
            for (int k0 = 0; k0 < A1; k0 += 16) {
                for (int i = tid; i < 16 * A2; i += NTHR) {
                    int kk = i >> 7, c = i & 127;
                    sm.b.w2t[kk][c] = w2[(k0 + kk) * A2 + c];
                }
                __syncthreads();
#pragma unroll
                for (int kk = 0; kk < 16; kk++) {
                    float a_[4];
#pragma unroll
                    for (int i = 0; i < 4; i++) a_[i] = sm.b.x1[ty * 4 + i][k0 + kk];
                    float4 wv = *reinterpret_cast<const float4*>(&sm.b.w2t[kk][tx * 4]);
#pragma unroll
                    for (int i = 0; i < 4; i++) {
                        acc[i][0] += a_[i] * wv.x;
                        acc[i][1] += a_[i] * wv.y;
                        acc[i][2] += a_[i] * wv.z;
                        acc[i][3] += a_[i] * wv.w;
                    }
                }
                __syncthreads();
            }
            float b2v0 = b2[tx * 4], b2v1 = b2[tx * 4 + 1], b2v2 = b2[tx * 4 + 2], b2v3 = b2[tx * 4 + 3];
            float w3v0 = w3[tx * 4], w3v1 = w3[tx * 4 + 1], w3v2 = w3[tx * 4 + 2], w3v3 = w3[tx * 4 + 3];
            float b3v = b3[0];
#pragma unroll
            for (int i = 0; i < 4; i++) {
                float p = tanhf(acc[i][0] + b2v0) * w3v0
                        + tanhf(acc[i][1] + b2v1) * w3v1
                        + tanhf(acc[i][2] + b2v2) * w3v2
                        + tanhf(acc[i][3] + b2v3) * w3v3;
#pragma unroll
                for (int off = 16; off; off >>= 1)
                    p += __shfl_down_sync(0xffffffffu, p, off);
                if (tx == 0) {
                    int l = l0 + ty * 4 + i;
                    if (l < LL) g_scores[b * LL + l] = p + b3v;
                }
            }
            __syncthreads();
        }
        grid_sync();

        // ---- Phase C: softmax + z. 64 units = 32 b x 2 d-chunks(256)
        if (bid < 64) {
            int b = bid >> 1;
            int dch = bid & 1;
            int lane = tid & 31, warp = tid >> 5;
            float v = (tid < LL) ? g_scores[b * LL + tid] : -1e30f;
            float m = v;
#pragma unroll
            for (int off = 16; off; off >>= 1) m = fmaxf(m, __shfl_xor_sync(0xffffffffu, m, off));
            if (lane == 0) sm.c.red[warp] = m;
            __syncthreads();
            m = sm.c.red[0];
#pragma unroll
            for (int i = 1; i < 8; i++) m = fmaxf(m, sm.c.red[i]);
            float e = (tid < LL) ? expf(v - m) : 0.f;
            __syncthreads();
            float sum = e;
#pragma unroll
            for (int off = 16; off; off >>= 1) sum += __shfl_xor_sync(0xffffffffu, sum, off);
            if (lane == 0) sm.c.red[warp] = sum;
            __syncthreads();
            sum = sm.c.red[0] + sm.c.red[1] + sm.c.red[2] + sm.c.red[3]
                + sm.c.red[4] + sm.c.red[5] + sm.c.red[6] + sm.c.red[7];
            float inv = 1.f / sum;
            if (tid < LL) sm.c.al[tid] = e * inv;
            __syncthreads();
            int d = dch * 256 + tid;    // 0..511
            float acc = 0.f;
            const float* ab = a_feat + (size_t)(b * LL) * DD + d;
#pragma unroll 4
            for (int l = 0; l < LL; l++) acc += sm.c.al[l] * ab[l * DD];
            g_z[b * DD + d] = acc;
            g_hze[(size_t)(b * TT + t) * HZE + HH + d] = acc;
        }
        grid_sync();

        // ---- Phase D: LSTM. 64 units = 8 jp-chunks(64) x 8 batch-groups(4)
        if (bid < 64) {
            int jpch = bid >> 3;        // 0..7
            int bg = bid & 7;           // 0..7
            for (int i = tid; i < 4 * DD; i += NTHR) {
                int bi = i >> 9, kk = i & 511;
                sm.d.z4[bi][kk] = g_z[(bg * 4 + bi) * DD + kk];
            }
            __syncthreads();
            int jl = tid & 63;          // jp local
            int gate = tid >> 6;        // 0..3 (i,f,g,o)
            int jp = jpch * 64 + jl;    // 0..511
            float acc0 = 0.f, acc1 = 0.f, acc2 = 0.f, acc3 = 0.f;
            const float* Wg = wih + (size_t)gate * HH + jp;
#pragma unroll 4
            for (int d = 0; d < DD; d++) {
                float w = Wg[(size_t)d * GG];
                acc0 += sm.d.z4[0][d] * w;
                acc1 += sm.d.z4[1][d] * w;
                acc2 += sm.d.z4[2][d] * w;
                acc3 += sm.d.z4[3][d] * w;
            }
            sm.d.gacc[gate][jl][0] = acc0;
            sm.d.gacc[gate][jl][1] = acc1;
            sm.d.gacc[gate][jl][2] = acc2;
            sm.d.gacc[gate][jl][3] = acc3;
            __syncthreads();
            // pointwise: thread = (jl, bi)
            int bi = tid >> 6;          // 0..3
            int b = bg * 4 + bi;
            const float* eg = g_egate + (size_t)(b * TT + t) * GG;
            const float* hg = g_hpg + b * NPG + A1;
            float ai = sm.d.gacc[0][jl][bi] + eg[jp]        + hg[jp];
            float af = sm.d.gacc[1][jl][bi] + eg[jp + 512]  + hg[jp + 512];
            float ag = sm.d.gacc[2][jl][bi] + eg[jp + 1024] + hg[jp + 1024];
            float ao = sm.d.gacc[3][jl][bi] + eg[jp + 1536] + hg[jp + 1536];
            float i_ = 1.f / (1.f + expf(-ai));
            float f_ = 1.f / (1.f + expf(-af));
            float o_ = 1.f / (1.f + expf(-ao));
            float gv = tanhf(ag);
            float c = f_ * g_c[b * HH + jp] + i_ * gv;
            float h = o_ * tanhf(c);
            g_c[b * HH + jp] = c;
            g_h[b * HH + jp] = h;
            g_hze[(size_t)(b * TT + t) * HZE + jp] = h;
        }
        grid_sync();
    }
}

// ---------------- launch ----------------
extern "C" void kernel_launch(void* const* d_in, const int* in_sizes, int n_in,
                              void* d_out, int out_size) {
    const float* a      = (const float*)d_in[0];
    const float* h0     = (const float*)d_in[1];
    const float* c0     = (const float*)d_in[2];
    const int*   y      = (const int*)d_in[3];
    const float* att_w1 = (const float*)d_in[4];
    const float* att_b1 = (const float*)d_in[5];
    const float* att_w2 = (const float*)d_in[6];
    const float* att_b2 = (const float*)d_in[7];
    const float* att_w3 = (const float*)d_in[8];
    const float* att_b3 = (const float*)d_in[9];
    const float* w_ih   = (const float*)d_in[10];
    const float* w_hh   = (const float*)d_in[11];
    const float* b_ih   = (const float*)d_in[12];
    const float* b_hh   = (const float*)d_in[13];
    const float* embed  = (const float*)d_in[14];
    const float* out_w1 = (const float*)d_in[15];
    const float* out_b1 = (const float*)d_in[16];
    const float* out_w2 = (const float*)d_in[17];
    const float* out_b2 = (const float*)d_in[18];
    const float* out_w3 = (const float*)d_in[19];
    const float* out_b3 = (const float*)d_in[20];
    float* out = (float*)d_out;

    float *prea, *eseq, *egate, *hze, *x1, *x2;
    cudaGetSymbolAddress((void**)&prea,  g_prea);
    cudaGetSymbolAddress((void**)&eseq,  g_eseq);
    cudaGetSymbolAddress((void**)&egate, g_egate);
    cudaGetSymbolAddress((void**)&hze,   g_hze);
    cudaGetSymbolAddress((void**)&x1,    g_x1);
    cudaGetSymbolAddress((void**)&x2,    g_x2);

    k_embed<<<BB * TT, EE>>>(y, embed);

    // pre_a[B*L,256] = a @ att_w1[:D] + b1
    k_sgemm<0><<<dim3((A1 + 63) / 64, (BB * LL + 63) / 64), 256>>>(
        a, DD, att_w1, A1, att_b1, prea, A1, BB * LL, A1, DD);
    // e_gates[B*T,2048] = e_seq @ w_ih[D:] + b_ih
    k_sgemm<0><<<dim3((GG + 63) / 64, (BB * TT + 63) / 64), 256>>>(
        eseq, EE, w_ih + (size_t)DD * GG, GG, b_ih, egate, GG, BB * TT, GG, EE);

    // persistent step loop (all 128 timesteps in one launch)
    k_steps<<<NBLK, NTHR>>>(a, h0, c0,
                            att_w1 + (size_t)DD * A1, w_hh, b_hh,
                            att_w2, att_b2, att_w3, att_b3, w_ih);

    // output MLP: (B*T,1280) -> 358 tanh -> 358 tanh -> V
    k_sgemm<1><<<dim3((NH + 63) / 64, (BB * TT + 63) / 64), 256>>>(
        hze, HZE, out_w1, NH, out_b1, x1, NH, BB * TT, NH, HZE);
    k_sgemm<1><<<dim3((NH + 63) / 64, (BB * TT + 63) / 64), 256>>>(
        x1, NH, out_w2, NH, out_b2, x2, NH, BB * TT, NH, NH);
    k_sgemm<0><<<dim3((VV + 63) / 64, (BB * TT + 63) / 64), 256>>>(
        x2, NH, out_w3, VV, out_b3, out, VV, BB * TT, VV, NH);
}

// round 8
// speedup vs baseline: 1.3736x; 1.0236x over previous
#include <cuda_runtime.h>
#include <math.h>

#define BB 32
#define LL 196
#define DD 512
#define HH 512
#define EE 256
#define TT 128
#define VV 512
#define A1 256
#define A2 128
#define GG 2048            // 4*H
#define NH 358
#define HZE (HH + DD + EE) // 1280
#define NPG (A1 + GG)      // 2304
#define PADTOK 0
#define NBLK 296
#define NTHR 256

// ---------------- scratch (no allocation allowed) ----------------
__device__ float g_eseq[BB * TT * EE];
__device__ float g_prea[BB * LL * A1];
__device__ float g_egate[BB * TT * GG];
__device__ float g_h[BB * HH];
__device__ float g_c[BB * HH];
__device__ float g_hpg[BB * NPG];
__device__ float g_scores[BB * LL];
__device__ float g_z[BB * DD];
__device__ float g_hze[BB * TT * HZE];
__device__ float g_x1[BB * TT * NH];
__device__ float g_x2[BB * TT * NH];

// ---------------- software grid barrier (generation counter) ----------------
__device__ unsigned g_bar_count;
__device__ volatile unsigned g_bar_gen;

__device__ __forceinline__ void grid_sync() {
    __syncthreads();
    if (threadIdx.x == 0) {
        unsigned gen = g_bar_gen;
        __threadfence();
        if (atomicAdd(&g_bar_count, 1u) == NBLK - 1) {
            g_bar_count = 0;
            __threadfence();
            g_bar_gen = gen + 1;
        } else {
            while (g_bar_gen == gen) {}
        }
        __threadfence();
    }
    __syncthreads();
}

// ---------------- embedding gather (shift-right w/ pad) ----------------
__global__ void k_embed(const int* __restrict__ y, const float* __restrict__ embed) {
    int bt = blockIdx.x;
    int b = bt / TT, t = bt % TT;
    int tok = (t == 0) ? PADTOK : y[b * TT + (t - 1)];
    float v = embed[tok * EE + threadIdx.x];
    g_eseq[bt * EE + threadIdx.x] = v;
    g_hze[bt * HZE + HH + DD + threadIdx.x] = v;
}

// ---------------- generic tiled SGEMM: C = act(A*W + bias) ----------------
template <int ACT>
__global__ void k_sgemm(const float* __restrict__ A, int lda,
                        const float* __restrict__ W, int ldw,
                        const float* __restrict__ bias,
                        float* __restrict__ C, int ldc,
                        int M, int N, int K) {
    __shared__ float As[16][65];
    __shared__ float Ws[16][65];
    int tx = threadIdx.x % 16, ty = threadIdx.x / 16;
    int row0 = blockIdx.y * 64;
    int col0 = blockIdx.x * 64;
    float acc[4][4] = {};
    for (int k0 = 0; k0 < K; k0 += 16) {
        for (int i = threadIdx.x; i < 64 * 16; i += 256) {
            int r = i >> 4, kk = i & 15;
            int gr = row0 + r, gk = k0 + kk;
            As[kk][r] = (gr < M && gk < K) ? A[gr * lda + gk] : 0.f;
        }
        for (int i = threadIdx.x; i < 16 * 64; i += 256) {
            int kk = i >> 6, c = i & 63;
            int gk = k0 + kk, gc = col0 + c;
            Ws[kk][c] = (gk < K && gc < N) ? W[gk * ldw + gc] : 0.f;
        }
        __syncthreads();
#pragma unroll
        for (int kk = 0; kk < 16; kk++) {
            float a_[4], w_[4];
#pragma unroll
            for (int i = 0; i < 4; i++) a_[i] = As[kk][ty * 4 + i];
#pragma unroll
            for (int j = 0; j < 4; j++) w_[j] = Ws[kk][tx * 4 + j];
#pragma unroll
            for (int i = 0; i < 4; i++)
#pragma unroll
                for (int j = 0; j < 4; j++) acc[i][j] += a_[i] * w_[j];
        }
        __syncthreads();
    }
#pragma unroll
    for (int i = 0; i < 4; i++) {
        int r = row0 + ty * 4 + i;
        if (r >= M) continue;
#pragma unroll
        for (int j = 0; j < 4; j++) {
            int c = col0 + tx * 4 + j;
            if (c >= N) continue;
            float v = acc[i][j] + (bias ? bias[c] : 0.f);
            if (ACT == 1) v = tanhf(v);
            C[r * ldc + c] = v;
        }
    }
}

// ---------------- persistent step-loop kernel ----------------
struct SmemA { float h4[4][HH]; };                                   // 8 KB
struct SmemB { __align__(16) float x1[16][A1];                       // 16 KB
               __align__(16) float w2t[16][A2];                      // 8 KB
               float hp[A1]; };                                      // 1 KB
struct SmemC { float al[LL]; float red[8]; };
struct SmemD { float z4[4][DD]; float gacc[4][64][4]; };             // 12 KB
union StepSmem { SmemA a; SmemB b; SmemC c; SmemD d; };

__global__ __launch_bounds__(NTHR, 2)
void k_steps(const float* __restrict__ a_feat,
             const float* __restrict__ h0, const float* __restrict__ c0,
             const float* __restrict__ w1h,   // att_w1 + D*A1 (ld A1)
             const float* __restrict__ whh,   // ld GG
             const float* __restrict__ bhh,
             const float* __restrict__ w2, const float* __restrict__ b2,
             const float* __restrict__ w3, const float* __restrict__ b3,
             const float* __restrict__ wih) {
    __shared__ StepSmem sm;
    int bid = blockIdx.x;
    int tid = threadIdx.x;

    for (int i = bid * NTHR + tid; i < BB * HH; i += NBLK * NTHR) {
        g_h[i] = h0[i];
        g_c[i] = c0[i];
    }
    grid_sync();

    for (int t = 0; t < TT; t++) {
        // ---- Phase A: hpg[b,0:256]=h@w1h ; hpg[b,256:2304]=h@whh+bhh
        // 144 units = 18 col-chunks(128) x 8 batch-groups(4)
        if (bid < 144) {
            int nch = bid / 8;
            int bg = bid % 8;
            for (int i = tid; i < 4 * HH; i += NTHR) {
                int bi = i >> 9, kk = i & 511;
                sm.a.h4[bi][kk] = g_h[(bg * 4 + bi) * HH + kk];
            }
            __syncthreads();
            int c = tid & 127;
            int half = tid >> 7;
            int n = nch * 128 + c;
            const float* W; int ld, col; float bias;
            if (n < A1) { W = w1h; ld = A1; col = n; bias = 0.f; }
            else        { W = whh; ld = GG; col = n - A1; bias = bhh[n - A1]; }
            int b0 = half * 2;
            float a0 = bias, a1 = bias;
#pragma unroll 4
            for (int k = 0; k < HH; k++) {
                float w = W[k * ld + col];
                a0 += sm.a.h4[b0][k] * w;
                a1 += sm.a.h4[b0 + 1][k] * w;
            }
            g_hpg[(bg * 4 + b0) * NPG + n] = a0;
            g_hpg[(bg * 4 + b0 + 1) * NPG + n] = a1;
        }
        grid_sync();

        // ---- Phase B: attention scores. 448 units = 32 b x 14 l-tiles(16)
        for (int u = bid; u < 448; u += NBLK) {
            int b = u / 14;
            int l0 = (u % 14) * 16;
            sm.b.hp[tid] = g_hpg[b * NPG + tid];   // tid < 256 == A1
            __syncthreads();
            for (int idx = tid; idx < 16 * A1; idx += NTHR) {
                int r = idx >> 8, k = idx & 255;
                int l = l0 + r;
                float v = 0.f;
                if (l < LL) v = tanhf(g_prea[(b * LL + l) * A1 + k] + sm.b.hp[k]);
                sm.b.x1[r][k] = v;
            }
            __syncthreads();
            int tx = tid & 31, ty = tid >> 5;      // warp ty -> rows ty*2, ty*2+1
            int r0 = ty * 2, r1 = ty * 2 + 1;
            float acc[2][4] = {};
            for (int k0 = 0; k0 < A1; k0 += 16) {
                for (int i = tid; i < 16 * A2; i += NTHR) {
                    int kk = i >> 7, c = i & 127;
                    sm.b.w2t[kk][c] = w2[(k0 + kk) * A2 + c];
                }
                __syncthreads();
#pragma unroll
                for (int kk = 0; kk < 16; kk++) {
                    float a0 = sm.b.x1[r0][k0 + kk];
                    float a1 = sm.b.x1[r1][k0 + kk];
                    float4 wv = *reinterpret_cast<const float4*>(&sm.b.w2t[kk][tx * 4]);
                    acc[0][0] += a0 * wv.x; acc[0][1] += a0 * wv.y;
                    acc[0][2] += a0 * wv.z; acc[0][3] += a0 * wv.w;
                    acc[1][0] += a1 * wv.x; acc[1][1] += a1 * wv.y;
                    acc[1][2] += a1 * wv.z; acc[1][3] += a1 * wv.w;
                }
                __syncthreads();
            }
            float b2v0 = b2[tx * 4], b2v1 = b2[tx * 4 + 1];
            float b2v2 = b2[tx * 4 + 2], b2v3 = b2[tx * 4 + 3];
            float w3v0 = w3[tx * 4], w3v1 = w3[tx * 4 + 1];
            float w3v2 = w3[tx * 4 + 2], w3v3 = w3[tx * 4 + 3];
            float b3v = b3[0];
#pragma unroll
            for (int i = 0; i < 2; i++) {
                float p = tanhf(acc[i][0] + b2v0) * w3v0
                        + tanhf(acc[i][1] + b2v1) * w3v1
                        + tanhf(acc[i][2] + b2v2) * w3v2
                        + tanhf(acc[i][3] + b2v3) * w3v3;
#pragma unroll
                for (int off = 16; off; off >>= 1)
                    p += __shfl_down_sync(0xffffffffu, p, off);
                if (tx == 0) {
                    int l = l0 + ty * 2 + i;
                    if (l < LL) g_scores[b * LL + l] = p + b3v;
                }
            }
            __syncthreads();
        }
        grid_sync();

        // ---- Phase C: softmax + z. 64 units = 32 b x 2 d-chunks(256)
        if (bid < 64) {
            int b = bid >> 1;
            int dch = bid & 1;
            int lane = tid & 31, warp = tid >> 5;
            float v = (tid < LL) ? g_scores[b * LL + tid] : -1e30f;
            float m = v;
#pragma unroll
            for (int off = 16; off; off >>= 1) m = fmaxf(m, __shfl_xor_sync(0xffffffffu, m, off));
            if (lane == 0) sm.c.red[warp] = m;
            __syncthreads();
            m = sm.c.red[0];
#pragma unroll
            for (int i = 1; i < 8; i++) m = fmaxf(m, sm.c.red[i]);
            float e = (tid < LL) ? expf(v - m) : 0.f;
            __syncthreads();
            float sum = e;
#pragma unroll
            for (int off = 16; off; off >>= 1) sum += __shfl_xor_sync(0xffffffffu, sum, off);
            if (lane == 0) sm.c.red[warp] = sum;
            __syncthreads();
            sum = sm.c.red[0] + sm.c.red[1] + sm.c.red[2] + sm.c.red[3]
                + sm.c.red[4] + sm.c.red[5] + sm.c.red[6] + sm.c.red[7];
            float inv = 1.f / sum;
            if (tid < LL) sm.c.al[tid] = e * inv;
            __syncthreads();
            int d = dch * 256 + tid;
            float acc = 0.f;
            const float* ab = a_feat + (size_t)(b * LL) * DD + d;
#pragma unroll 4
            for (int l = 0; l < LL; l++) acc += sm.c.al[l] * ab[l * DD];
            g_z[b * DD + d] = acc;
            g_hze[(size_t)(b * TT + t) * HZE + HH + d] = acc;
        }
        grid_sync();

        // ---- Phase D: LSTM. 64 units = 8 jp-chunks(64) x 8 batch-groups(4)
        if (bid < 64) {
            int jpch = bid >> 3;
            int bg = bid & 7;
            for (int i = tid; i < 4 * DD; i += NTHR) {
                int bi = i >> 9, kk = i & 511;
                sm.d.z4[bi][kk] = g_z[(bg * 4 + bi) * DD + kk];
            }
            __syncthreads();
            int jl = tid & 63;
            int gate = tid >> 6;
            int jp = jpch * 64 + jl;
            float acc0 = 0.f, acc1 = 0.f, acc2 = 0.f, acc3 = 0.f;
            const float* Wg = wih + (size_t)gate * HH + jp;
#pragma unroll 4
            for (int d = 0; d < DD; d++) {
                float w = Wg[(size_t)d * GG];
                acc0 += sm.d.z4[0][d] * w;
                acc1 += sm.d.z4[1][d] * w;
                acc2 += sm.d.z4[2][d] * w;
                acc3 += sm.d.z4[3][d] * w;
            }
            sm.d.gacc[gate][jl][0] = acc0;
            sm.d.gacc[gate][jl][1] = acc1;
            sm.d.gacc[gate][jl][2] = acc2;
            sm.d.gacc[gate][jl][3] = acc3;
            __syncthreads();
            int bi = tid >> 6;
            int b = bg * 4 + bi;
            const float* eg = g_egate + (size_t)(b * TT + t) * GG;
            const float* hg = g_hpg + b * NPG + A1;
            float ai = sm.d.gacc[0][jl][bi] + eg[jp]        + hg[jp];
            float af = sm.d.gacc[1][jl][bi] + eg[jp + 512]  + hg[jp + 512];
            float ag = sm.d.gacc[2][jl][bi] + eg[jp + 1024] + hg[jp + 1024];
            float ao = sm.d.gacc[3][jl][bi] + eg[jp + 1536] + hg[jp + 1536];
            float i_ = 1.f / (1.f + expf(-ai));
            float f_ = 1.f / (1.f + expf(-af));
            float o_ = 1.f / (1.f + expf(-ao));
            float gv = tanhf(ag);
            float c = f_ * g_c[b * HH + jp] + i_ * gv;
            float h = o_ * tanhf(c);
            g_c[b * HH + jp] = c;
            g_h[b * HH + jp] = h;
            g_hze[(size_t)(b * TT + t) * HZE + jp] = h;
        }
        grid_sync();
    }
}

// ---------------- launch ----------------
extern "C" void kernel_launch(void* const* d_in, const int* in_sizes, int n_in,
                              void* d_out, int out_size) {
    const float* a      = (const float*)d_in[0];
    const float* h0     = (const float*)d_in[1];
    const float* c0     = (const float*)d_in[2];
    const int*   y      = (const int*)d_in[3];
    const float* att_w1 = (const float*)d_in[4];
    const float* att_b1 = (const float*)d_in[5];
    const float* att_w2 = (const float*)d_in[6];
    const float* att_b2 = (const float*)d_in[7];
    const float* att_w3 = (const float*)d_in[8];
    const float* att_b3 = (const float*)d_in[9];
    const float* w_ih   = (const float*)d_in[10];
    const float* w_hh   = (const float*)d_in[11];
    const float* b_ih   = (const float*)d_in[12];
    const float* b_hh   = (const float*)d_in[13];
    const float* embed  = (const float*)d_in[14];
    const float* out_w1 = (const float*)d_in[15];
    const float* out_b1 = (const float*)d_in[16];
    const float* out_w2 = (const float*)d_in[17];
    const float* out_b2 = (const float*)d_in[18];
    const float* out_w3 = (const float*)d_in[19];
    const float* out_b3 = (const float*)d_in[20];
    float* out = (float*)d_out;

    float *prea, *eseq, *egate, *hze, *x1, *x2;
    cudaGetSymbolAddress((void**)&prea,  g_prea);
    cudaGetSymbolAddress((void**)&eseq,  g_eseq);
    cudaGetSymbolAddress((void**)&egate, g_egate);
    cudaGetSymbolAddress((void**)&hze,   g_hze);
    cudaGetSymbolAddress((void**)&x1,    g_x1);
    cudaGetSymbolAddress((void**)&x2,    g_x2);

    k_embed<<<BB * TT, EE>>>(y, embed);

    k_sgemm<0><<<dim3((A1 + 63) / 64, (BB * LL + 63) / 64), 256>>>(
        a, DD, att_w1, A1, att_b1, prea, A1, BB * LL, A1, DD);
    k_sgemm<0><<<dim3((GG + 63) / 64, (BB * TT + 63) / 64), 256>>>(
        eseq, EE, w_ih + (size_t)DD * GG, GG, b_ih, egate, GG, BB * TT, GG, EE);

    k_steps<<<NBLK, NTHR>>>(a, h0, c0,
                            att_w1 + (size_t)DD * A1, w_hh, b_hh,
                            att_w2, att_b2, att_w3, att_b3, w_ih);

    k_sgemm<1><<<dim3((NH + 63) / 64, (BB * TT + 63) / 64), 256>>>(
        hze, HZE, out_w1, NH, out_b1, x1, NH, BB * TT, NH, HZE);
    k_sgemm<1><<<dim3((NH + 63) / 64, (BB * TT + 63) / 64), 256>>>(
        x1, NH, out_w2, NH, out_b2, x2, NH, BB * TT, NH, NH);
    k_sgemm<0><<<dim3((VV + 63) / 64, (BB * TT + 63) / 64), 256>>>(
        x2, NH, out_w3, VV, out_b3, out, VV, BB * TT, VV, NH);
}

// round 9
// speedup vs baseline: 1.5993x; 1.1644x over previous
#include <cuda_runtime.h>
#include <math.h>

#define BB 32
#define LL 196
#define DD 512
#define HH 512
#define EE 256
#define TT 128
#define VV 512
#define A1 256
#define A2 128
#define GG 2048            // 4*H
#define NH 358
#define HZE (HH + DD + EE) // 1280
#define NPG (A1 + GG)      // 2304
#define PADTOK 0
#define NBLK 296
#define NTHR 256
#define X1PAD 36           // padded row length for transposed x1 tile

// ---------------- scratch (no allocation allowed) ----------------
__device__ float g_eseq[BB * TT * EE];
__device__ float g_prea[BB * LL * A1];
__device__ float g_egate[BB * TT * GG];
__device__ float g_h[BB * HH];
__device__ float g_c[BB * HH];
__device__ float g_hpg[BB * NPG];
__device__ float g_scores[BB * LL];
__device__ float g_z[BB * DD];
__device__ float g_hze[BB * TT * HZE];
__device__ float g_x1[BB * TT * NH];
__device__ float g_x2[BB * TT * NH];

// ---------------- software grid barrier (generation counter) ----------------
__device__ unsigned g_bar_count;
__device__ volatile unsigned g_bar_gen;

__device__ __forceinline__ void grid_sync() {
    __syncthreads();
    if (threadIdx.x == 0) {
        unsigned gen = g_bar_gen;
        __threadfence();
        if (atomicAdd(&g_bar_count, 1u) == NBLK - 1) {
            g_bar_count = 0;
            __threadfence();
            g_bar_gen = gen + 1;
        } else {
            while (g_bar_gen == gen) {}
        }
        __threadfence();
    }
    __syncthreads();
}

// ---------------- embedding gather (shift-right w/ pad) ----------------
__global__ void k_embed(const int* __restrict__ y, const float* __restrict__ embed) {
    int bt = blockIdx.x;
    int b = bt / TT, t = bt % TT;
    int tok = (t == 0) ? PADTOK : y[b * TT + (t - 1)];
    float v = embed[tok * EE + threadIdx.x];
    g_eseq[bt * EE + threadIdx.x] = v;
    g_hze[bt * HZE + HH + DD + threadIdx.x] = v;
}

// ---------------- generic tiled SGEMM: C = act(A*W + bias) ----------------
template <int ACT>
__global__ void k_sgemm(const float* __restrict__ A, int lda,
                        const float* __restrict__ W, int ldw,
                        const float* __restrict__ bias,
                        float* __restrict__ C, int ldc,
                        int M, int N, int K) {
    __shared__ float As[16][65];
    __shared__ float Ws[16][65];
    int tx = threadIdx.x % 16, ty = threadIdx.x / 16;
    int row0 = blockIdx.y * 64;
    int col0 = blockIdx.x * 64;
    float acc[4][4] = {};
    for (int k0 = 0; k0 < K; k0 += 16) {
        for (int i = threadIdx.x; i < 64 * 16; i += 256) {
            int r = i >> 4, kk = i & 15;
            int gr = row0 + r, gk = k0 + kk;
            As[kk][r] = (gr < M && gk < K) ? A[gr * lda + gk] : 0.f;
        }
        for (int i = threadIdx.x; i < 16 * 64; i += 256) {
            int kk = i >> 6, c = i & 63;
            int gk = k0 + kk, gc = col0 + c;
            Ws[kk][c] = (gk < K && gc < N) ? W[gk * ldw + gc] : 0.f;
        }
        __syncthreads();
#pragma unroll
        for (int kk = 0; kk < 16; kk++) {
            float a_[4], w_[4];
#pragma unroll
            for (int i = 0; i < 4; i++) a_[i] = As[kk][ty * 4 + i];
#pragma unroll
            for (int j = 0; j < 4; j++) w_[j] = Ws[kk][tx * 4 + j];
#pragma unroll
            for (int i = 0; i < 4; i++)
#pragma unroll
                for (int j = 0; j < 4; j++) acc[i][j] += a_[i] * w_[j];
        }
        __syncthreads();
    }
#pragma unroll
    for (int i = 0; i < 4; i++) {
        int r = row0 + ty * 4 + i;
        if (r >= M) continue;
#pragma unroll
        for (int j = 0; j < 4; j++) {
            int c = col0 + tx * 4 + j;
            if (c >= N) continue;
            float v = acc[i][j] + (bias ? bias[c] : 0.f);
            if (ACT == 1) v = tanhf(v);
            C[r * ldc + c] = v;
        }
    }
}

// ---------------- persistent step-loop kernel ----------------
struct SmemA1 { float h1[HH]; };
struct SmemA2 { float h4[4][HH]; };                                  // 8 KB
struct SmemB  { __align__(16) float x1t[A1][X1PAD];                  // 36.9 KB
                float hp[A1]; };
struct SmemC  { float al[LL]; float red[8]; float cpart[2][128]; };
struct SmemD  { float zs[4][DD]; float gacc[4][4][16]; };            // 9.2 KB
union StepSmem { SmemA1 a1; SmemA2 a2; SmemB b; SmemC c; SmemD d; };

__global__ __launch_bounds__(NTHR, 2)
void k_steps(const float* __restrict__ a_feat,
             const float* __restrict__ h0, const float* __restrict__ c0,
             const float* __restrict__ w1h,   // att_w1 + D*A1 (ld A1)
             const float* __restrict__ whh,   // ld GG
             const float* __restrict__ bhh,
             const float* __restrict__ w2, const float* __restrict__ b2,
             const float* __restrict__ w3, const float* __restrict__ b3,
             const float* __restrict__ wih) {
    __shared__ StepSmem sm;
    int bid = blockIdx.x;
    int tid = threadIdx.x;

    for (int i = bid * NTHR + tid; i < BB * HH; i += NBLK * NTHR) {
        g_h[i] = h0[i];
        g_c[i] = c0[i];
    }
    grid_sync();

    for (int t = 0; t < TT; t++) {
        // ======== Phase 1: A1 (32 units) + A2 (128 units) ========
        if (bid < 32) {
            // A1: hpg[b, 0:256] = h[b] @ w1h
            int b = bid;
            for (int i = tid; i < HH; i += NTHR) sm.a1.h1[i] = g_h[b * HH + i];
            __syncthreads();
            float acc = 0.f;
#pragma unroll 16
            for (int k = 0; k < HH; k++)
                acc += sm.a1.h1[k] * w1h[k * A1 + tid];
            g_hpg[b * NPG + tid] = acc;
        } else if (bid < 160) {
            // A2: hpg[b, 256:2304] = h[b] @ whh + bhh
            int a2u = bid - 32;
            int nch = a2u >> 3;               // 0..15 (128-col chunk)
            int bg = a2u & 7;                 // 4 batches
            for (int i = tid; i < 4 * HH; i += NTHR) {
                int bi = i >> 9, kk = i & 511;
                sm.a2.h4[bi][kk] = g_h[(bg * 4 + bi) * HH + kk];
            }
            __syncthreads();
            int col = nch * 128 + (tid & 127);   // 0..2047
            int b0 = (tid >> 7) * 2;
            float bias = bhh[col];
            float acc0 = bias, acc1 = bias;
#pragma unroll 16
            for (int k = 0; k < HH; k++) {
                float w = whh[k * GG + col];
                acc0 += sm.a2.h4[b0][k] * w;
                acc1 += sm.a2.h4[b0 + 1][k] * w;
            }
            g_hpg[(bg * 4 + b0) * NPG + A1 + col] = acc0;
            g_hpg[(bg * 4 + b0 + 1) * NPG + A1 + col] = acc1;
        }
        grid_sync();

        // ======== Phase 2: attention (224 units = 32 b x 7 l-tiles(32)) ========
        if (bid < 224) {
            int b = bid / 7;
            int l0 = (bid % 7) * 32;
            sm.b.hp[tid] = g_hpg[b * NPG + tid];   // tid < 256 == A1
            __syncthreads();
            // fill transposed x1 tile: x1t[k][r] = tanh(prea[l0+r][k] + hp[k])
            for (int idx = tid; idx < 32 * A1; idx += NTHR) {
                int r = idx >> 8, k = idx & 255;
                int l = l0 + r;
                float v = 0.f;
                if (l < LL) v = tanhf(g_prea[(b * LL + l) * A1 + k] + sm.b.hp[k]);
                sm.b.x1t[k][r] = v;
            }
            __syncthreads();
            int tx = tid & 31, ty = tid >> 5;      // warp ty -> rows ty*4..+3
            float acc[4][4] = {};
            const float4* w2v = reinterpret_cast<const float4*>(w2);
#pragma unroll 8
            for (int k = 0; k < A1; k++) {
                float4 av = *reinterpret_cast<const float4*>(&sm.b.x1t[k][ty * 4]);
                float4 wv = w2v[k * (A2 / 4) + tx];
                acc[0][0] += av.x * wv.x; acc[0][1] += av.x * wv.y;
                acc[0][2] += av.x * wv.z; acc[0][3] += av.x * wv.w;
                acc[1][0] += av.y * wv.x; acc[1][1] += av.y * wv.y;
                acc[1][2] += av.y * wv.z; acc[1][3] += av.y * wv.w;
                acc[2][0] += av.z * wv.x; acc[2][1] += av.z * wv.y;
                acc[2][2] += av.z * wv.z; acc[2][3] += av.z * wv.w;
                acc[3][0] += av.w * wv.x; acc[3][1] += av.w * wv.y;
                acc[3][2] += av.w * wv.z; acc[3][3] += av.w * wv.w;
            }
            float b2v0 = b2[tx * 4], b2v1 = b2[tx * 4 + 1];
            float b2v2 = b2[tx * 4 + 2], b2v3 = b2[tx * 4 + 3];
            float w3v0 = w3[tx * 4], w3v1 = w3[tx * 4 + 1];
            float w3v2 = w3[tx * 4 + 2], w3v3 = w3[tx * 4 + 3];
            float b3v = b3[0];
#pragma unroll
            for (int i = 0; i < 4; i++) {
                float p = tanhf(acc[i][0] + b2v0) * w3v0
                        + tanhf(acc[i][1] + b2v1) * w3v1
                        + tanhf(acc[i][2] + b2v2) * w3v2
                        + tanhf(acc[i][3] + b2v3) * w3v3;
#pragma unroll
                for (int off = 16; off; off >>= 1)
                    p += __shfl_down_sync(0xffffffffu, p, off);
                if (tx == 0) {
                    int l = l0 + ty * 4 + i;
                    if (l < LL) g_scores[b * LL + l] = p + b3v;
                }
            }
        }
        grid_sync();

        // ======== Phase 3: softmax + z (128 units = 32 b x 4 d-chunks(128)) ====
        if (bid < 128) {
            int b = bid >> 2;
            int dch = bid & 3;
            int lane = tid & 31, warp = tid >> 5;
            float v = (tid < LL) ? g_scores[b * LL + tid] : -1e30f;
            float m = v;
#pragma unroll
            for (int off = 16; off; off >>= 1) m = fmaxf(m, __shfl_xor_sync(0xffffffffu, m, off));
            if (lane == 0) sm.c.red[warp] = m;
            __syncthreads();
            m = sm.c.red[0];
#pragma unroll
            for (int i = 1; i < 8; i++) m = fmaxf(m, sm.c.red[i]);
            float e = (tid < LL) ? expf(v - m) : 0.f;
            __syncthreads();
            float sum = e;
#pragma unroll
            for (int off = 16; off; off >>= 1) sum += __shfl_xor_sync(0xffffffffu, sum, off);
            if (lane == 0) sm.c.red[warp] = sum;
            __syncthreads();
            sum = sm.c.red[0] + sm.c.red[1] + sm.c.red[2] + sm.c.red[3]
                + sm.c.red[4] + sm.c.red[5] + sm.c.red[6] + sm.c.red[7];
            float inv = 1.f / sum;
            if (tid < LL) sm.c.al[tid] = e * inv;
            __syncthreads();
            // context: thread = (l-half, local d); 98 l's each
            int dl = tid & 127;
            int lh = tid >> 7;
            int d = dch * 128 + dl;
            const float* ab = a_feat + (size_t)(b * LL + lh * 98) * DD + d;
            const float* alv = &sm.c.al[lh * 98];
            float acc = 0.f;
#pragma unroll 14
            for (int l = 0; l < 98; l++) acc += alv[l] * ab[(size_t)l * DD];
            sm.c.cpart[lh][dl] = acc;
            __syncthreads();
            if (tid < 128) {
                float zv = sm.c.cpart[0][tid] + sm.c.cpart[1][tid];
                int dg = dch * 128 + tid;
                g_z[b * DD + dg] = zv;
                g_hze[(size_t)(b * TT + t) * HZE + HH + dg] = zv;
            }
        }
        grid_sync();

        // ======== Phase 4: LSTM (256 units = 32 jp-chunks(16) x 8 bg(4)) ========
        if (bid < 256) {
            int jpch = bid >> 3;              // 0..31
            int bg = bid & 7;                 // 0..7
            for (int i = tid; i < 4 * DD; i += NTHR) {
                int bi = i >> 9, kk = i & 511;
                sm.d.zs[bi][kk] = g_z[(bg * 4 + bi) * DD + kk];
            }
            __syncthreads();
            int jl = tid & 15;
            int gate = (tid >> 4) & 3;
            int bi = tid >> 6;
            int jp = jpch * 16 + jl;
            const float* Wg = wih + (size_t)gate * HH + jp;
            const float* zrow = sm.d.zs[bi];
            float acc = 0.f;
#pragma unroll 16
            for (int d = 0; d < DD; d++)
                acc += zrow[d] * Wg[(size_t)d * GG];
            sm.d.gacc[gate][bi][jl] = acc;
            __syncthreads();
            if (tid < 64) {
                int jl2 = tid & 15;
                int bi2 = tid >> 4;
                int b = bg * 4 + bi2;
                int jp2 = jpch * 16 + jl2;
                const float* eg = g_egate + (size_t)(b * TT + t) * GG;
                const float* hg = g_hpg + b * NPG + A1;
                float ai = sm.d.gacc[0][bi2][jl2] + eg[jp2]        + hg[jp2];
                float af = sm.d.gacc[1][bi2][jl2] + eg[jp2 + 512]  + hg[jp2 + 512];
                float ag = sm.d.gacc[2][bi2][jl2] + eg[jp2 + 1024] + hg[jp2 + 1024];
                float ao = sm.d.gacc[3][bi2][jl2] + eg[jp2 + 1536] + hg[jp2 + 1536];
                float i_ = 1.f / (1.f + expf(-ai));
                float f_ = 1.f / (1.f + expf(-af));
                float o_ = 1.f / (1.f + expf(-ao));
                float gv = tanhf(ag);
                float c = f_ * g_c[b * HH + jp2] + i_ * gv;
                float h = o_ * tanhf(c);
                g_c[b * HH + jp2] = c;
                g_h[b * HH + jp2] = h;
                g_hze[(size_t)(b * TT + t) * HZE + jp2] = h;
            }
        }
        grid_sync();
    }
}

// ---------------- launch ----------------
extern "C" void kernel_launch(void* const* d_in, const int* in_sizes, int n_in,
                              void* d_out, int out_size) {
    const float* a      = (const float*)d_in[0];
    const float* h0     = (const float*)d_in[1];
    const float* c0     = (const float*)d_in[2];
    const int*   y      = (const int*)d_in[3];
    const float* att_w1 = (const float*)d_in[4];
    const float* att_b1 = (const float*)d_in[5];
    const float* att_w2 = (const float*)d_in[6];
    const float* att_b2 = (const float*)d_in[7];
    const float* att_w3 = (const float*)d_in[8];
    const float* att_b3 = (const float*)d_in[9];
    const float* w_ih   = (const float*)d_in[10];
    const float* w_hh   = (const float*)d_in[11];
    const float* b_ih   = (const float*)d_in[12];
    const float* b_hh   = (const float*)d_in[13];
    const float* embed  = (const float*)d_in[14];
    const float* out_w1 = (const float*)d_in[15];
    const float* out_b1 = (const float*)d_in[16];
    const float* out_w2 = (const float*)d_in[17];
    const float* out_b2 = (const float*)d_in[18];
    const float* out_w3 = (const float*)d_in[19];
    const float* out_b3 = (const float*)d_in[20];
    float* out = (float*)d_out;

    float *prea, *eseq, *egate, *hze, *x1, *x2;
    cudaGetSymbolAddress((void**)&prea,  g_prea);
    cudaGetSymbolAddress((void**)&eseq,  g_eseq);
    cudaGetSymbolAddress((void**)&egate, g_egate);
    cudaGetSymbolAddress((void**)&hze,   g_hze);
    cudaGetSymbolAddress((void**)&x1,    g_x1);
    cudaGetSymbolAddress((void**)&x2,    g_x2);

    k_embed<<<BB * TT, EE>>>(y, embed);

    k_sgemm<0><<<dim3((A1 + 63) / 64, (BB * LL + 63) / 64), 256>>>(
        a, DD, att_w1, A1, att_b1, prea, A1, BB * LL, A1, DD);
    k_sgemm<0><<<dim3((GG + 63) / 64, (BB * TT + 63) / 64), 256>>>(
        eseq, EE, w_ih + (size_t)DD * GG, GG, b_ih, egate, GG, BB * TT, GG, EE);

    k_steps<<<NBLK, NTHR>>>(a, h0, c0,
                            att_w1 + (size_t)DD * A1, w_hh, b_hh,
                            att_w2, att_b2, att_w3, att_b3, w_ih);

    k_sgemm<1><<<dim3((NH + 63) / 64, (BB * TT + 63) / 64), 256>>>(
        hze, HZE, out_w1, NH, out_b1, x1, NH, BB * TT, NH, HZE);
    k_sgemm<1><<<dim3((NH + 63) / 64, (BB * TT + 63) / 64), 256>>>(
        x1, NH, out_w2, NH, out_b2, x2, NH, BB * TT, NH, NH);
    k_sgemm<0><<<dim3((VV + 63) / 64, (BB * TT + 63) / 64), 256>>>(
        x2, NH, out_w3, VV, out_b3, out, VV, BB * TT, VV, NH);
}

// round 10
// speedup vs baseline: 2.4191x; 1.5125x over previous
#include <cuda_runtime.h>
#include <math.h>

#define BB 32
#define LL 196
#define DD 512
#define HH 512
#define EE 256
#define TT 128
#define VV 512
#define A1 256
#define A2 128
#define GG 2048            // 4*H
#define NH 358
#define HZE (HH + DD + EE) // 1280
#define NPG (A1 + GG)      // 2304
#define PADTOK 0
#define NBLK 296
#define NTHR 256
#define X1PAD 36           // padded row length for transposed x1 tile (16B-aligned rows)

// ---------------- scratch (no allocation allowed) ----------------
__device__ float g_eseq[BB * TT * EE];
__device__ float g_prea[BB * LL * A1];
__device__ float g_egate[BB * TT * GG];
__device__ float g_h[BB * HH];
__device__ float g_c[BB * HH];
__device__ float g_hpg[BB * NPG];
__device__ float g_scores[BB * LL];
__device__ float g_z[BB * DD];
__device__ float g_hze[BB * TT * HZE];
__device__ float g_x1[BB * TT * NH];
__device__ float g_x2[BB * TT * NH];

// ---------------- software grid barrier (generation counter) ----------------
__device__ unsigned g_bar_count;
__device__ volatile unsigned g_bar_gen;

__device__ __forceinline__ void grid_sync() {
    __syncthreads();
    if (threadIdx.x == 0) {
        unsigned gen = g_bar_gen;
        __threadfence();
        if (atomicAdd(&g_bar_count, 1u) == NBLK - 1) {
            g_bar_count = 0;
            __threadfence();
            g_bar_gen = gen + 1;
        } else {
            while (g_bar_gen == gen) {}
        }
        __threadfence();
    }
    __syncthreads();
}

// ---------------- embedding gather (shift-right w/ pad) ----------------
__global__ void k_embed(const int* __restrict__ y, const float* __restrict__ embed) {
    int bt = blockIdx.x;
    int b = bt / TT, t = bt % TT;
    int tok = (t == 0) ? PADTOK : y[b * TT + (t - 1)];
    float v = embed[tok * EE + threadIdx.x];
    g_eseq[bt * EE + threadIdx.x] = v;
    g_hze[bt * HZE + HH + DD + threadIdx.x] = v;
}

// ---------------- generic tiled SGEMM: C = act(A*W + bias) ----------------
template <int ACT>
__global__ void k_sgemm(const float* __restrict__ A, int lda,
                        const float* __restrict__ W, int ldw,
                        const float* __restrict__ bias,
                        float* __restrict__ C, int ldc,
                        int M, int N, int K) {
    __shared__ float As[16][65];
    __shared__ float Ws[16][65];
    int tx = threadIdx.x % 16, ty = threadIdx.x / 16;
    int row0 = blockIdx.y * 64;
    int col0 = blockIdx.x * 64;
    float acc[4][4] = {};
    for (int k0 = 0; k0 < K; k0 += 16) {
        for (int i = threadIdx.x; i < 64 * 16; i += 256) {
            int r = i >> 4, kk = i & 15;
            int gr = row0 + r, gk = k0 + kk;
            As[kk][r] = (gr < M && gk < K) ? A[gr * lda + gk] : 0.f;
        }
        for (int i = threadIdx.x; i < 16 * 64; i += 256) {
            int kk = i >> 6, c = i & 63;
            int gk = k0 + kk, gc = col0 + c;
            Ws[kk][c] = (gk < K && gc < N) ? W[gk * ldw + gc] : 0.f;
        }
        __syncthreads();
#pragma unroll
        for (int kk = 0; kk < 16; kk++) {
            float a_[4], w_[4];
#pragma unroll
            for (int i = 0; i < 4; i++) a_[i] = As[kk][ty * 4 + i];
#pragma unroll
            for (int j = 0; j < 4; j++) w_[j] = Ws[kk][tx * 4 + j];
#pragma unroll
            for (int i = 0; i < 4; i++)
#pragma unroll
                for (int j = 0; j < 4; j++) acc[i][j] += a_[i] * w_[j];
        }
        __syncthreads();
    }
#pragma unroll
    for (int i = 0; i < 4; i++) {
        int r = row0 + ty * 4 + i;
        if (r >= M) continue;
#pragma unroll
        for (int j = 0; j < 4; j++) {
            int c = col0 + tx * 4 + j;
            if (c >= N) continue;
            float v = acc[i][j] + (bias ? bias[c] : 0.f);
            if (ACT == 1) v = tanhf(v);
            C[r * ldc + c] = v;
        }
    }
}

// ---------------- persistent step-loop kernel ----------------
struct SmemA { float h4[4][HH]; };                                   // 8 KB
struct SmemB { __align__(16) float x1t[A1][X1PAD];                   // 36 KB
               float hp[A1];                                         // 1 KB
               float red[32][4]; };                                  // 0.5 KB
struct SmemC { float al[LL]; float red[8]; float cpart[2][128]; };
struct SmemD { float zs[4][DD]; float gacc[4][4][16]; };             // 9.2 KB
union StepSmem { SmemA a; SmemB b; SmemC c; SmemD d; };

__global__ __launch_bounds__(NTHR, 2)
void k_steps(const float* __restrict__ a_feat,
             const float* __restrict__ h0, const float* __restrict__ c0,
             const float* __restrict__ w1h,   // att_w1 + D*A1 (ld A1)
             const float* __restrict__ whh,   // ld GG
             const float* __restrict__ bhh,
             const float* __restrict__ w2, const float* __restrict__ b2,
             const float* __restrict__ w3, const float* __restrict__ b3,
             const float* __restrict__ wih) {
    __shared__ StepSmem sm;
    int bid = blockIdx.x;
    int tid = threadIdx.x;

    for (int i = bid * NTHR + tid; i < BB * HH; i += NBLK * NTHR) {
        g_h[i] = h0[i];
        g_c[i] = c0[i];
    }
    grid_sync();

    for (int t = 0; t < TT; t++) {
        // ======== Phase A: h projections, 288 units = 36 col-chunks(64) x 8 bg(4)
        if (bid < 288) {
            int cch = bid >> 3;               // 0..35
            int bg = bid & 7;                 // 0..7
            for (int i = tid; i < 4 * HH; i += NTHR) {
                int bi = i >> 9, kk = i & 511;
                sm.a.h4[bi][kk] = g_h[(bg * 4 + bi) * HH + kk];
            }
            __syncthreads();
            int col = tid & 63;
            int bi = tid >> 6;                // 0..3
            int n = cch * 64 + col;           // 0..2303
            const float* W; int ld; float acc;
            if (n < A1) { W = w1h + n; ld = A1; acc = 0.f; }
            else        { W = whh + (n - A1); ld = GG; acc = bhh[n - A1]; }
            const float* hrow = sm.a.h4[bi];
#pragma unroll 32
            for (int k = 0; k < HH; k++)
                acc += hrow[k] * W[(size_t)k * ld];
            g_hpg[(bg * 4 + bi) * NPG + n] = acc;
        }
        grid_sync();

        // ======== Phase B: attention (224 units = 32 b x 7 l-tiles(32)) ========
        // warp tiling: warp = 16 rows x 32 cols; lane = (rg = l>>3 -> 4 rows, cq = l&7 -> 4 cols)
        if (bid < 224) {
            int b = bid / 7;
            int l0 = (bid % 7) * 32;
            sm.b.hp[tid] = g_hpg[b * NPG + tid];   // tid < 256 == A1
            __syncthreads();
            for (int idx = tid; idx < 32 * A1; idx += NTHR) {
                int r = idx >> 8, k = idx & 255;
                int l = l0 + r;
                float v = 0.f;
                if (l < LL) v = tanhf(g_prea[(b * LL + l) * A1 + k] + sm.b.hp[k]);
                sm.b.x1t[k][r] = v;
            }
            __syncthreads();
            int lane = tid & 31, w = tid >> 5;      // 8 warps
            int rh = w & 1, ch = w >> 1;            // row-half (16), col-quarter (32)
            int rg = lane >> 3, cq = lane & 7;
            int r0 = rh * 16 + rg * 4;              // first of this lane's 4 rows
            int c0 = ch * 32 + cq * 4;              // first of this lane's 4 cols
            float acc[4][4] = {};
#pragma unroll 4
            for (int k = 0; k < A1; k++) {
                float4 av = *reinterpret_cast<const float4*>(&sm.b.x1t[k][r0]);
                float4 wv = *reinterpret_cast<const float4*>(&w2[k * A2 + c0]);
                acc[0][0] += av.x * wv.x; acc[0][1] += av.x * wv.y;
                acc[0][2] += av.x * wv.z; acc[0][3] += av.x * wv.w;
                acc[1][0] += av.y * wv.x; acc[1][1] += av.y * wv.y;
                acc[1][2] += av.y * wv.z; acc[1][3] += av.y * wv.w;
                acc[2][0] += av.z * wv.x; acc[2][1] += av.z * wv.y;
                acc[2][2] += av.z * wv.z; acc[2][3] += av.z * wv.w;
                acc[3][0] += av.w * wv.x; acc[3][1] += av.w * wv.y;
                acc[3][2] += av.w * wv.z; acc[3][3] += av.w * wv.w;
            }
            float b2v0 = b2[c0], b2v1 = b2[c0 + 1], b2v2 = b2[c0 + 2], b2v3 = b2[c0 + 3];
            float w3v0 = w3[c0], w3v1 = w3[c0 + 1], w3v2 = w3[c0 + 2], w3v3 = w3[c0 + 3];
#pragma unroll
            for (int i = 0; i < 4; i++) {
                float p = tanhf(acc[i][0] + b2v0) * w3v0
                        + tanhf(acc[i][1] + b2v1) * w3v1
                        + tanhf(acc[i][2] + b2v2) * w3v2
                        + tanhf(acc[i][3] + b2v3) * w3v3;
                p += __shfl_down_sync(0xffffffffu, p, 4, 8);
                p += __shfl_down_sync(0xffffffffu, p, 2, 8);
                p += __shfl_down_sync(0xffffffffu, p, 1, 8);
                if (cq == 0) sm.b.red[r0 + i][ch] = p;
            }
            __syncthreads();
            if (tid < 32) {
                int l = l0 + tid;
                if (l < LL) {
                    float s = sm.b.red[tid][0] + sm.b.red[tid][1]
                            + sm.b.red[tid][2] + sm.b.red[tid][3] + b3[0];
                    g_scores[b * LL + l] = s;
                }
            }
        }
        grid_sync();

        // ======== Phase C: softmax + z (128 units = 32 b x 4 d-chunks(128)) ====
        if (bid < 128) {
            int b = bid >> 2;
            int dch = bid & 3;
            int lane = tid & 31, warp = tid >> 5;
            float v = (tid < LL) ? g_scores[b * LL + tid] : -1e30f;
            float m = v;
#pragma unroll
            for (int off = 16; off; off >>= 1) m = fmaxf(m, __shfl_xor_sync(0xffffffffu, m, off));
            if (lane == 0) sm.c.red[warp] = m;
            __syncthreads();
            m = sm.c.red[0];
#pragma unroll
            for (int i = 1; i < 8; i++) m = fmaxf(m, sm.c.red[i]);
            float e = (tid < LL) ? expf(v - m) : 0.f;
            __syncthreads();
            float sum = e;
#pragma unroll
            for (int off = 16; off; off >>= 1) sum += __shfl_xor_sync(0xffffffffu, sum, off);
            if (lane == 0) sm.c.red[warp] = sum;
            __syncthreads();
            sum = sm.c.red[0] + sm.c.red[1] + sm.c.red[2] + sm.c.red[3]
                + sm.c.red[4] + sm.c.red[5] + sm.c.red[6] + sm.c.red[7];
            float inv = 1.f / sum;
            if (tid < LL) sm.c.al[tid] = e * inv;
            __syncthreads();
            int dl = tid & 127;
            int lh = tid >> 7;
            int d = dch * 128 + dl;
            const float* ab = a_feat + (size_t)(b * LL + lh * 98) * DD + d;
            const float* alv = &sm.c.al[lh * 98];
            float acc = 0.f;
#pragma unroll 14
            for (int l = 0; l < 98; l++) acc += alv[l] * ab[(size_t)l * DD];
            sm.c.cpart[lh][dl] = acc;
            __syncthreads();
            if (tid < 128) {
                float zv = sm.c.cpart[0][tid] + sm.c.cpart[1][tid];
                int dg = dch * 128 + tid;
                g_z[b * DD + dg] = zv;
                g_hze[(size_t)(b * TT + t) * HZE + HH + dg] = zv;
            }
        }
        grid_sync();

        // ======== Phase D: LSTM (256 units = 32 jp-chunks(16) x 8 bg(4)) ========
        if (bid < 256) {
            int jpch = bid >> 3;              // 0..31
            int bg = bid & 7;                 // 0..7
            for (int i = tid; i < 4 * DD; i += NTHR) {
                int bi = i >> 9, kk = i & 511;
                sm.d.zs[bi][kk] = g_z[(bg * 4 + bi) * DD + kk];
            }
            __syncthreads();
            int jl = tid & 15;
            int gate = (tid >> 4) & 3;
            int bi = tid >> 6;
            int jp = jpch * 16 + jl;
            const float* Wg = wih + (size_t)gate * HH + jp;
            const float* zrow = sm.d.zs[bi];
            float acc = 0.f;
#pragma unroll 32
            for (int d = 0; d < DD; d++)
                acc += zrow[d] * Wg[(size_t)d * GG];
            sm.d.gacc[gate][bi][jl] = acc;
            __syncthreads();
            if (tid < 64) {
                int jl2 = tid & 15;
                int bi2 = tid >> 4;
                int b = bg * 4 + bi2;
                int jp2 = jpch * 16 + jl2;
                const float* eg = g_egate + (size_t)(b * TT + t) * GG;
                const float* hg = g_hpg + b * NPG + A1;
                float ai = sm.d.gacc[0][bi2][jl2] + eg[jp2]        + hg[jp2];
                float af = sm.d.gacc[1][bi2][jl2] + eg[jp2 + 512]  + hg[jp2 + 512];
                float ag = sm.d.gacc[2][bi2][jl2] + eg[jp2 + 1024] + hg[jp2 + 1024];
                float ao = sm.d.gacc[3][bi2][jl2] + eg[jp2 + 1536] + hg[jp2 + 1536];
                float i_ = 1.f / (1.f + expf(-ai));
                float f_ = 1.f / (1.f + expf(-af));
                float o_ = 1.f / (1.f + expf(-ao));
                float gv = tanhf(ag);
                float c = f_ * g_c[b * HH + jp2] + i_ * gv;
                float h = o_ * tanhf(c);
                g_c[b * HH + jp2] = c;
                g_h[b * HH + jp2] = h;
                g_hze[(size_t)(b * TT + t) * HZE + jp2] = h;
            }
        }
        grid_sync();
    }
}

// ---------------- launch ----------------
extern "C" void kernel_launch(void* const* d_in, const int* in_sizes, int n_in,
                              void* d_out, int out_size) {
    const float* a      = (const float*)d_in[0];
    const float* h0     = (const float*)d_in[1];
    const float* c0     = (const float*)d_in[2];
    const int*   y      = (const int*)d_in[3];
    const float* att_w1 = (const float*)d_in[4];
    const float* att_b1 = (const float*)d_in[5];
    const float* att_w2 = (const float*)d_in[6];
    const float* att_b2 = (const float*)d_in[7];
    const float* att_w3 = (const float*)d_in[8];
    const float* att_b3 = (const float*)d_in[9];
    const float* w_ih   = (const float*)d_in[10];
    const float* w_hh   = (const float*)d_in[11];
    const float* b_ih   = (const float*)d_in[12];
    const float* b_hh   = (const float*)d_in[13];
    const float* embed  = (const float*)d_in[14];
    const float* out_w1 = (const float*)d_in[15];
    const float* out_b1 = (const float*)d_in[16];
    const float* out_w2 = (const float*)d_in[17];
    const float* out_b2 = (const float*)d_in[18];
    const float* out_w3 = (const float*)d_in[19];
    const float* out_b3 = (const float*)d_in[20];
    float* out = (float*)d_out;

    float *prea, *eseq, *egate, *hze, *x1, *x2;
    cudaGetSymbolAddress((void**)&prea,  g_prea);
    cudaGetSymbolAddress((void**)&eseq,  g_eseq);
    cudaGetSymbolAddress((void**)&egate, g_egate);
    cudaGetSymbolAddress((void**)&hze,   g_hze);
    cudaGetSymbolAddress((void**)&x1,    g_x1);
    cudaGetSymbolAddress((void**)&x2,    g_x2);

    k_embed<<<BB * TT, EE>>>(y, embed);

    k_sgemm<0><<<dim3((A1 + 63) / 64, (BB * LL + 63) / 64), 256>>>(
        a, DD, att_w1, A1, att_b1, prea, A1, BB * LL, A1, DD);
    k_sgemm<0><<<dim3((GG + 63) / 64, (BB * TT + 63) / 64), 256>>>(
        eseq, EE, w_ih + (size_t)DD * GG, GG, b_ih, egate, GG, BB * TT, GG, EE);

    k_steps<<<NBLK, NTHR>>>(a, h0, c0,
                            att_w1 + (size_t)DD * A1, w_hh, b_hh,
                            att_w2, att_b2, att_w3, att_b3, w_ih);

    k_sgemm<1><<<dim3((NH + 63) / 64, (BB * TT + 63) / 64), 256>>>(
        hze, HZE, out_w1, NH, out_b1, x1, NH, BB * TT, NH, HZE);
    k_sgemm<1><<<dim3((NH + 63) / 64, (BB * TT + 63) / 64), 256>>>(
        x1, NH, out_w2, NH, out_b2, x2, NH, BB * TT, NH, NH);
    k_sgemm<0><<<dim3((VV + 63) / 64, (BB * TT + 63) / 64), 256>>>(
        x2, NH, out_w3, VV, out_b3, out, VV, BB * TT, VV, NH);
}